// round 11
// baseline (speedup 1.0000x reference)
#include <cuda_runtime.h>
#include <stdint.h>
#include <math.h>

#define Bn 32
#define Sn 512
#define Hn 768
#define FDn 64
#define Pn 30
#define NROWS (Bn*Sn)    // 16384

// ------------------ scratch ------------------
__device__ float g_WT [Hn * 32];          // W_t transposed [k][p], zero-padded p
__device__ float g_WaT[FDn * 32];         // W_a transposed [k][p]
__device__ float g_textT [Bn * 32 * Sn];  // [b][p][s]
__device__ float g_audioT[Bn * 32 * Sn];  // [b][p][s]
__device__ float g_part[256];             // block partial sums of text^2
__device__ float g_raw0[Bn * Sn];
__device__ float g_prob[Bn * Sn];
__device__ float g_avp[Bn * 16 * Hn];

// ------------------ K0a/K0b/K0c: transpose weights (split for profiling alignment) ------------------
__global__ void k_prep_t0(const float* __restrict__ Wt) {
    int e = blockIdx.x * 256 + threadIdx.x;      // 48 blocks: first 12288
    int p = e & 31, k = e >> 5;
    g_WT[e] = (p < Pn) ? Wt[p * Hn + k] : 0.f;
}
__global__ void k_prep_t1(const float* __restrict__ Wt) {
    int e = 12288 + blockIdx.x * 256 + threadIdx.x;   // 48 blocks: second 12288
    int p = e & 31, k = e >> 5;
    g_WT[e] = (p < Pn) ? Wt[p * Hn + k] : 0.f;
}
__global__ void k_prep_a(const float* __restrict__ Wa) {
    int e = blockIdx.x * 256 + threadIdx.x;      // 8 blocks: 2048
    int p = e & 31, k = e >> 5;
    g_WaT[e] = (p < Pn) ? Wa[p * FDn + k] : 0.f;
}

// ------------------ K1: projection GEMM, cp.async double-buffered ------------------
// grid 256, block 256. Block: 64 rows x 32 p. Thread: 2r x 4p.
#define FSTEP(Ai, i)                                                        \
    acc[i][0] += Ai.x*W0.x + Ai.y*W1.x + Ai.z*W2.x + Ai.w*W3.x;             \
    acc[i][1] += Ai.x*W0.y + Ai.y*W1.y + Ai.z*W2.y + Ai.w*W3.y;             \
    acc[i][2] += Ai.x*W0.z + Ai.y*W1.z + Ai.z*W2.z + Ai.w*W3.z;             \
    acc[i][3] += Ai.x*W0.w + Ai.y*W1.w + Ai.z*W2.w + Ai.w*W3.w;

__device__ __forceinline__ void cp16(unsigned int dst, const void* src) {
    asm volatile("cp.async.cg.shared.global [%0], [%1], 16;" :: "r"(dst), "l"(src));
}

__global__ __launch_bounds__(256) void k_proj(const float* __restrict__ hs,
                                              const float* __restrict__ ad) {
    __shared__ __align__(16) float sA[2][64 * 64];   // 32 KB
    __shared__ __align__(16) float sW[2][64 * 32];   // 16 KB  (total 48 KB)
    int tid = threadIdx.x;
    int pg = tid & 7, rg = tid >> 3;       // p = pg*4+j, r = rg*2+i
    int row0 = blockIdx.x * 64;
    int b = row0 >> 9, s0 = row0 & 511;
    const float4* hs4 = (const float4*)hs;
    const float4* gW4 = (const float4*)g_WT;

    unsigned int aA[2], aW[2];
    aA[0] = (unsigned int)__cvta_generic_to_shared(&sA[0][0]);
    aA[1] = (unsigned int)__cvta_generic_to_shared(&sA[1][0]);
    aW[0] = (unsigned int)__cvta_generic_to_shared(&sW[0][0]);
    aW[1] = (unsigned int)__cvta_generic_to_shared(&sW[1][0]);

    int rL = tid >> 4, cL = tid & 15;      // A-load coords (16 rows per q-step)

    // prefetch chunk 0
    #pragma unroll
    for (int q = 0; q < 4; q++) {
        int r = rL + 16 * q;
        cp16(aA[0] + (unsigned int)(r * 64 + cL * 4) * 4,
             &hs4[(size_t)(row0 + r) * 192 + cL]);
    }
    #pragma unroll
    for (int q = 0; q < 2; q++) {
        int e = tid + 256 * q;
        cp16(aW[0] + (unsigned int)e * 16, &gW4[e]);
    }
    asm volatile("cp.async.commit_group;");

    float acc[2][4];
    #pragma unroll
    for (int i = 0; i < 2; i++)
        #pragma unroll
        for (int j = 0; j < 4; j++) acc[i][j] = 0.f;

    for (int kc = 0; kc < 12; kc++) {
        int cur = kc & 1;
        if (kc < 11) {
            int nb = cur ^ 1;
            #pragma unroll
            for (int q = 0; q < 4; q++) {
                int r = rL + 16 * q;
                cp16(aA[nb] + (unsigned int)(r * 64 + cL * 4) * 4,
                     &hs4[(size_t)(row0 + r) * 192 + (kc + 1) * 16 + cL]);
            }
            #pragma unroll
            for (int q = 0; q < 2; q++) {
                int e = tid + 256 * q;
                cp16(aW[nb] + (unsigned int)e * 16, &gW4[(kc + 1) * 512 + e]);
            }
            asm volatile("cp.async.commit_group;");
            asm volatile("cp.async.wait_group 1;");
        } else {
            asm volatile("cp.async.wait_group 0;");
        }
        __syncthreads();

        const float* pA = sA[cur];
        const float* pW = sW[cur];
        #pragma unroll
        for (int kk = 0; kk < 16; kk++) {
            int k = kk * 4;
            float4 A0 = *(const float4*)&pA[(rg * 2 + 0) * 64 + k];
            float4 A1 = *(const float4*)&pA[(rg * 2 + 1) * 64 + k];
            float4 W0 = *(const float4*)&pW[(k + 0) * 32 + pg * 4];
            float4 W1 = *(const float4*)&pW[(k + 1) * 32 + pg * 4];
            float4 W2 = *(const float4*)&pW[(k + 2) * 32 + pg * 4];
            float4 W3 = *(const float4*)&pW[(k + 3) * 32 + pg * 4];
            FSTEP(A0, 0) FSTEP(A1, 1)
        }
        __syncthreads();
    }

    float sumsq = 0.f;
    #pragma unroll
    for (int i = 0; i < 2; i++)
        #pragma unroll
        for (int j = 0; j < 4; j++) {
            sumsq += acc[i][j] * acc[i][j];
            int p = pg * 4 + j, s = s0 + rg * 2 + i;
            g_textT[((size_t)(b * 32 + p)) * 512 + s] = acc[i][j];
        }

    // ---- audio: K=64, one chunk, plain loads into buffer 0 ----
    #pragma unroll
    for (int i = 0; i < 2; i++)
        #pragma unroll
        for (int j = 0; j < 4; j++) acc[i][j] = 0.f;
    #pragma unroll
    for (int q = 0; q < 4; q++) {
        int e = tid + 256 * q;
        int r = e >> 4, c = e & 15;
        float4 v = ((const float4*)ad)[(size_t)(row0 + r) * 16 + c];
        *(float4*)&sA[0][r * 64 + c * 4] = v;
    }
    #pragma unroll
    for (int q = 0; q < 2; q++) {
        int e = tid + 256 * q;
        ((float4*)&sW[0][0])[e] = ((const float4*)g_WaT)[e];
    }
    __syncthreads();
    #pragma unroll
    for (int kk = 0; kk < 16; kk++) {
        int k = kk * 4;
        float4 A0 = *(const float4*)&sA[0][(rg * 2 + 0) * 64 + k];
        float4 A1 = *(const float4*)&sA[0][(rg * 2 + 1) * 64 + k];
        float4 W0 = *(const float4*)&sW[0][(k + 0) * 32 + pg * 4];
        float4 W1 = *(const float4*)&sW[0][(k + 1) * 32 + pg * 4];
        float4 W2 = *(const float4*)&sW[0][(k + 2) * 32 + pg * 4];
        float4 W3 = *(const float4*)&sW[0][(k + 3) * 32 + pg * 4];
        FSTEP(A0, 0) FSTEP(A1, 1)
    }
    #pragma unroll
    for (int i = 0; i < 2; i++)
        #pragma unroll
        for (int j = 0; j < 4; j++) {
            int p = pg * 4 + j, s = s0 + rg * 2 + i;
            g_audioT[((size_t)(b * 32 + p)) * 512 + s] = acc[i][j];
        }

    // ---- sumsq block reduce (overlay on sW[1]) ----
    __syncthreads();
    float* red = &sW[1][0];
    red[tid] = sumsq;
    __syncthreads();
    for (int s = 128; s > 0; s >>= 1) {
        if (tid < s) red[tid] += red[tid + s];
        __syncthreads();
    }
    if (tid == 0) g_part[blockIdx.x] = red[0];
}

// ------------------ K3: symmetric score matrices (+ norm prologue) ------------------
// grid (36 upper-tri tile pairs, 32 b), 256 threads, 64x64 tiles, 4x4 micro.
__global__ __launch_bounds__(256) void k_scores(const float* __restrict__ twp,
                                                const float* __restrict__ awp,
                                                const float* __restrict__ fbp,
                                                float* __restrict__ out_ta,
                                                float* __restrict__ out_fa) {
    __shared__ float sTs[32 * 64], sTt[32 * 64], sAs[32 * 64], sAt[32 * 64];
    __shared__ float scs;
    int x = blockIdx.x, si = 0;
    while (x >= 8 - si) { x -= 8 - si; si++; }
    int ti = si + x;
    int b = blockIdx.y;
    int s0 = si * 64, t0 = ti * 64;
    int tid = threadIdx.x;

    // norm-scale prologue (256 partials)
    if (tid < 32) {
        float v = 0.f;
        #pragma unroll
        for (int j = 0; j < 8; j++) v += g_part[tid + 32 * j];
        #pragma unroll
        for (int o = 16; o > 0; o >>= 1) v += __shfl_xor_sync(0xffffffff, v, o);
        if (tid == 0) scs = rsqrtf(v);
    }

    const float4* gT = (const float4*)(g_textT  + (size_t)b * 32 * 512);
    const float4* gA = (const float4*)(g_audioT + (size_t)b * 32 * 512);
    #pragma unroll
    for (int q = 0; q < 2; q++) {
        int e = tid + 256 * q;              // 512 float4 per array
        int p = e >> 4, c = e & 15;
        *(float4*)&sTs[p * 64 + c * 4] = gT[p * 128 + (s0 >> 2) + c];
        *(float4*)&sTt[p * 64 + c * 4] = gT[p * 128 + (t0 >> 2) + c];
        *(float4*)&sAs[p * 64 + c * 4] = gA[p * 128 + (s0 >> 2) + c];
        *(float4*)&sAt[p * 64 + c * 4] = gA[p * 128 + (t0 >> 2) + c];
    }
    __syncthreads();

    int tx = tid & 15, ty = tid >> 4;
    float st[16], sa[16];
    #pragma unroll
    for (int i = 0; i < 16; i++) { st[i] = 0.f; sa[i] = 0.f; }

    #pragma unroll 6
    for (int p = 0; p < Pn; p++) {
        float4 a = *(float4*)&sTs[p * 64 + ty * 4];
        float4 bt = *(float4*)&sTt[p * 64 + tx * 4];
        float4 c = *(float4*)&sAs[p * 64 + ty * 4];
        float4 d = *(float4*)&sAt[p * 64 + tx * 4];
        st[0]  += a.x*bt.x; st[1]  += a.x*bt.y; st[2]  += a.x*bt.z; st[3]  += a.x*bt.w;
        st[4]  += a.y*bt.x; st[5]  += a.y*bt.y; st[6]  += a.y*bt.z; st[7]  += a.y*bt.w;
        st[8]  += a.z*bt.x; st[9]  += a.z*bt.y; st[10] += a.z*bt.z; st[11] += a.z*bt.w;
        st[12] += a.w*bt.x; st[13] += a.w*bt.y; st[14] += a.w*bt.z; st[15] += a.w*bt.w;
        sa[0]  += c.x*d.x;  sa[1]  += c.x*d.y;  sa[2]  += c.x*d.z;  sa[3]  += c.x*d.w;
        sa[4]  += c.y*d.x;  sa[5]  += c.y*d.y;  sa[6]  += c.y*d.z;  sa[7]  += c.y*d.w;
        sa[8]  += c.z*d.x;  sa[9]  += c.z*d.y;  sa[10] += c.z*d.z;  sa[11] += c.z*d.w;
        sa[12] += c.w*d.x;  sa[13] += c.w*d.y;  sa[14] += c.w*d.z;  sa[15] += c.w*d.w;
    }

    float cs = scs;
    float tw = twp[0], aw = awp[0], fb = fbp[0];
    float ta[16], fa[16];
    float rw[4];
    #pragma unroll
    for (int i = 0; i < 4; i++)
        #pragma unroll
        for (int j = 0; j < 4; j++) {
            float t_ = fmaxf(st[i * 4 + j] * cs, 0.f);
            float a_ = fmaxf(sa[i * 4 + j], 0.f);
            float r_ = tw * t_ + aw * a_ + fb;
            ta[i * 4 + j] = t_;
            fa[i * 4 + j] = fmaxf(r_, 0.f);
            if (i == 0) rw[j] = r_;
        }

    // normal store [s][t]
    #pragma unroll
    for (int i = 0; i < 4; i++) {
        int s = s0 + ty * 4 + i;
        size_t base = ((size_t)(b * Sn + s)) * Sn + t0 + tx * 4;
        *(float4*)(out_ta + base) = make_float4(ta[i*4], ta[i*4+1], ta[i*4+2], ta[i*4+3]);
        *(float4*)(out_fa + base) = make_float4(fa[i*4], fa[i*4+1], fa[i*4+2], fa[i*4+3]);
    }
    if (si == 0 && ty == 0)
        *(float4*)(g_raw0 + b * Sn + t0 + tx * 4) =
            make_float4(rw[0], rw[1], rw[2], rw[3]);

    // mirror store [t][s]
    if (si != ti) {
        #pragma unroll
        for (int j = 0; j < 4; j++) {
            int t = t0 + tx * 4 + j;
            size_t base = ((size_t)(b * Sn + t)) * Sn + s0 + ty * 4;
            *(float4*)(out_ta + base) = make_float4(ta[j], ta[4+j], ta[8+j], ta[12+j]);
            *(float4*)(out_fa + base) = make_float4(fa[j], fa[4+j], fa[8+j], fa[12+j]);
        }
    }
}

// ------------------ K4: softmax probs for s=0 row ------------------
__global__ __launch_bounds__(256) void k_soft(const float* __restrict__ am) {
    __shared__ float red[256];
    int b = blockIdx.x, tid = threadIdx.x;
    float mbase = am[b * Sn];
    float l0 = g_raw0[b * Sn + tid]       + am[b * Sn + tid]       + mbase;
    float l1 = g_raw0[b * Sn + tid + 256] + am[b * Sn + tid + 256] + mbase;

    red[tid] = fmaxf(l0, l1);
    __syncthreads();
    for (int s = 128; s > 0; s >>= 1) {
        if (tid < s) red[tid] = fmaxf(red[tid], red[tid + s]);
        __syncthreads();
    }
    float mx = red[0];
    __syncthreads();
    float e0 = expf(l0 - mx), e1 = expf(l1 - mx);
    red[tid] = e0 + e1;
    __syncthreads();
    for (int s = 128; s > 0; s >>= 1) {
        if (tid < s) red[tid] += red[tid + s];
        __syncthreads();
    }
    float inv = 1.f / red[0];
    g_prob[b * Sn + tid]       = e0 * inv;
    g_prob[b * Sn + tid + 256] = e1 * inv;
}

// ------------------ K5: att @ hidden ------------------
__global__ __launch_bounds__(192) void k_av(const float* __restrict__ hs) {
    __shared__ float sp[32];
    int b = blockIdx.x, cy = blockIdx.y, tid = threadIdx.x;
    int t0 = cy * 32;
    if (tid < 32) sp[tid] = g_prob[b * Sn + t0 + tid];
    __syncthreads();

    const float4* hb = (const float4*)(hs + (size_t)b * Sn * Hn);
    float4 acc = make_float4(0.f, 0.f, 0.f, 0.f);
    #pragma unroll 4
    for (int t = 0; t < 32; t++) {
        float p = sp[t];
        float4 h = hb[(size_t)(t0 + t) * 192 + tid];
        acc.x += p * h.x; acc.y += p * h.y; acc.z += p * h.z; acc.w += p * h.w;
    }
    ((float4*)g_avp)[(size_t)(b * 16 + cy) * 192 + tid] = acc;
}

// ------------------ K6: dense GEMV + layernorm fused ------------------
// grid 32 (one block per batch), 256 threads
__global__ __launch_bounds__(256) void k_denseln(const float* __restrict__ hs,
                                                 const float* __restrict__ Wd,
                                                 const float* __restrict__ bd,
                                                 const float* __restrict__ lw,
                                                 const float* __restrict__ lb,
                                                 float* __restrict__ out0) {
    __shared__ float sx[Hn];
    __shared__ float sh[Hn];
    __shared__ float red[256];
    int b = blockIdx.x, tid = threadIdx.x;
    int w = tid >> 5, lane = tid & 31;

    for (int i = tid; i < Hn; i += 256) {
        float v = hs[(size_t)b * Sn * Hn + i];
        #pragma unroll
        for (int c = 0; c < 16; c++) v += g_avp[(size_t)(b * 16 + c) * Hn + i];
        sx[i] = v;
    }
    __syncthreads();

    const float4* sx4 = (const float4*)sx;
    for (int q = 0; q < 96; q++) {
        int o = w * 96 + q;
        const float4* w4 = (const float4*)(Wd + (size_t)o * Hn);
        float acc = 0.f;
        #pragma unroll
        for (int c = 0; c < 6; c++) {
            float4 wv = w4[c * 32 + lane];
            float4 xv = sx4[c * 32 + lane];
            acc += wv.x * xv.x + wv.y * xv.y + wv.z * xv.z + wv.w * xv.w;
        }
        #pragma unroll
        for (int s = 16; s > 0; s >>= 1)
            acc += __shfl_down_sync(0xffffffff, acc, s);
        if (lane == 0) sh[o] = acc + bd[o];
    }
    __syncthreads();

    float hv[3];
    #pragma unroll
    for (int j = 0; j < 3; j++) hv[j] = sh[tid + 256 * j];
    red[tid] = hv[0] + hv[1] + hv[2];
    __syncthreads();
    for (int s = 128; s > 0; s >>= 1) {
        if (tid < s) red[tid] += red[tid + s];
        __syncthreads();
    }
    float u = red[0] / (float)Hn;
    __syncthreads();
    float vs = 0.f;
    #pragma unroll
    for (int j = 0; j < 3; j++) { float d = hv[j] - u; vs += d * d; }
    red[tid] = vs;
    __syncthreads();
    for (int s = 128; s > 0; s >>= 1) {
        if (tid < s) red[tid] += red[tid + s];
        __syncthreads();
    }
    float rstd = rsqrtf(red[0] / (float)Hn + 1e-12f);
    #pragma unroll
    for (int j = 0; j < 3; j++) {
        int o = tid + 256 * j;
        out0[b * Hn + o] = lw[o] * (hv[j] - u) * rstd + lb[o];
    }
}

// ------------------ launch ------------------
extern "C" void kernel_launch(void* const* d_in, const int* in_sizes, int n_in,
                              void* d_out, int out_size) {
    const float* hs = (const float*)d_in[0];
    const float* ad = (const float*)d_in[1];
    const float* am = (const float*)d_in[2];
    const float* Wt = (const float*)d_in[3];
    const float* Wa = (const float*)d_in[4];
    const float* tw = (const float*)d_in[5];
    const float* aw = (const float*)d_in[6];
    const float* fb = (const float*)d_in[7];
    const float* Wd = (const float*)d_in[8];
    const float* bd = (const float*)d_in[9];
    const float* lw = (const float*)d_in[10];
    const float* lb = (const float*)d_in[11];

    float* out    = (float*)d_out;
    float* out_h0 = out;
    float* out_ta = out + Bn * Hn;
    float* out_fa = out + Bn * Hn + (size_t)Bn * Sn * Sn;

    k_prep_t0<<<48, 256>>>(Wt);
    k_prep_t1<<<48, 256>>>(Wt);
    k_prep_a<<<8, 256>>>(Wa);
    k_proj<<<256, 256>>>(hs, ad);             // 4th launch -> gets profiled
    k_scores<<<dim3(36, 32), 256>>>(tw, aw, fb, out_ta, out_fa);
    k_soft<<<32, 256>>>(am);
    k_av<<<dim3(32, 16), 192>>>(hs);
    k_denseln<<<32, 256>>>(hs, Wd, bd, lw, lb, out_h0);
}

// round 12
// speedup vs baseline: 1.6688x; 1.6688x over previous
#include <cuda_runtime.h>
#include <stdint.h>
#include <math.h>

#define Bn 32
#define Sn 512
#define Hn 768
#define FDn 64
#define Pn 30
#define NROWS (Bn*Sn)    // 16384

// ------------------ scratch ------------------
__device__ float g_WT [Hn * 32];          // W_t transposed [k][p], zero-padded p
__device__ float g_WaT[FDn * 32];         // W_a transposed [k][p]
__device__ float g_textT [Bn * 32 * Sn];  // [b][p][s]
__device__ float g_audioT[Bn * 32 * Sn];  // [b][p][s]
__device__ float g_part[256];             // block partial sums of text^2
__device__ float g_raw0[Bn * Sn];
__device__ float g_prob[Bn * Sn];
__device__ float g_avp[Bn * 16 * Hn];
__device__ float g_h[Bn * Hn];

// ------------------ K0a/K0b/K0c: transpose weights ------------------
__global__ void k_prep_t0(const float* __restrict__ Wt) {
    int e = blockIdx.x * 256 + threadIdx.x;      // first 12288
    int p = e & 31, k = e >> 5;
    g_WT[e] = (p < Pn) ? Wt[p * Hn + k] : 0.f;
}
__global__ void k_prep_t1(const float* __restrict__ Wt) {
    int e = 12288 + blockIdx.x * 256 + threadIdx.x;   // second 12288
    int p = e & 31, k = e >> 5;
    g_WT[e] = (p < Pn) ? Wt[p * Hn + k] : 0.f;
}
__global__ void k_prep_a(const float* __restrict__ Wa) {
    int e = blockIdx.x * 256 + threadIdx.x;      // 2048
    int p = e & 31, k = e >> 5;
    g_WaT[e] = (p < Pn) ? Wa[p * FDn + k] : 0.f;
}

// ------------------ K1: projection GEMM, cp.async double-buffered, pitch-68 A ------------------
// grid 256, block 256. Block: 64 rows x 32 p. Thread: 2r x 4p.
#define APITCH 68
#define FSTEP(Ai, i)                                                        \
    acc[i][0] += Ai.x*W0.x + Ai.y*W1.x + Ai.z*W2.x + Ai.w*W3.x;             \
    acc[i][1] += Ai.x*W0.y + Ai.y*W1.y + Ai.z*W2.y + Ai.w*W3.y;             \
    acc[i][2] += Ai.x*W0.z + Ai.y*W1.z + Ai.z*W2.z + Ai.w*W3.z;             \
    acc[i][3] += Ai.x*W0.w + Ai.y*W1.w + Ai.z*W2.w + Ai.w*W3.w;

__device__ __forceinline__ void cp16(unsigned int dst, const void* src) {
    asm volatile("cp.async.cg.shared.global [%0], [%1], 16;" :: "r"(dst), "l"(src));
}

__global__ __launch_bounds__(256) void k_proj(const float* __restrict__ hs,
                                              const float* __restrict__ ad) {
    __shared__ __align__(16) float sA[2][64 * APITCH];   // 34 KB
    __shared__ __align__(16) float sW[2][64 * 32];       // 16 KB
    int tid = threadIdx.x;
    int pg = tid & 7, rg = tid >> 3;       // p = pg*4+j, r = rg*2+i
    int row0 = blockIdx.x * 64;
    int b = row0 >> 9, s0 = row0 & 511;
    const float4* hs4 = (const float4*)hs;
    const float4* gW4 = (const float4*)g_WT;

    unsigned int aA[2], aW[2];
    aA[0] = (unsigned int)__cvta_generic_to_shared(&sA[0][0]);
    aA[1] = (unsigned int)__cvta_generic_to_shared(&sA[1][0]);
    aW[0] = (unsigned int)__cvta_generic_to_shared(&sW[0][0]);
    aW[1] = (unsigned int)__cvta_generic_to_shared(&sW[1][0]);

    int rL = tid >> 4, cL = tid & 15;      // A-load coords

    // prefetch chunk 0
    #pragma unroll
    for (int q = 0; q < 4; q++) {
        int r = rL + 16 * q;
        cp16(aA[0] + (unsigned int)(r * APITCH + cL * 4) * 4,
             &hs4[(size_t)(row0 + r) * 192 + cL]);
    }
    #pragma unroll
    for (int q = 0; q < 2; q++) {
        int e = tid + 256 * q;
        cp16(aW[0] + (unsigned int)e * 16, &gW4[e]);
    }
    asm volatile("cp.async.commit_group;");

    float acc[2][4];
    #pragma unroll
    for (int i = 0; i < 2; i++)
        #pragma unroll
        for (int j = 0; j < 4; j++) acc[i][j] = 0.f;

    for (int kc = 0; kc < 12; kc++) {
        int cur = kc & 1;
        if (kc < 11) {
            int nb = cur ^ 1;
            #pragma unroll
            for (int q = 0; q < 4; q++) {
                int r = rL + 16 * q;
                cp16(aA[nb] + (unsigned int)(r * APITCH + cL * 4) * 4,
                     &hs4[(size_t)(row0 + r) * 192 + (kc + 1) * 16 + cL]);
            }
            #pragma unroll
            for (int q = 0; q < 2; q++) {
                int e = tid + 256 * q;
                cp16(aW[nb] + (unsigned int)e * 16, &gW4[(kc + 1) * 512 + e]);
            }
            asm volatile("cp.async.commit_group;");
            asm volatile("cp.async.wait_group 1;");
        } else {
            asm volatile("cp.async.wait_group 0;");
        }
        __syncthreads();

        const float* pA = sA[cur];
        const float* pW = sW[cur];
        #pragma unroll
        for (int kk = 0; kk < 16; kk++) {
            int k = kk * 4;
            float4 A0 = *(const float4*)&pA[(rg * 2 + 0) * APITCH + k];
            float4 A1 = *(const float4*)&pA[(rg * 2 + 1) * APITCH + k];
            float4 W0 = *(const float4*)&pW[(k + 0) * 32 + pg * 4];
            float4 W1 = *(const float4*)&pW[(k + 1) * 32 + pg * 4];
            float4 W2 = *(const float4*)&pW[(k + 2) * 32 + pg * 4];
            float4 W3 = *(const float4*)&pW[(k + 3) * 32 + pg * 4];
            FSTEP(A0, 0) FSTEP(A1, 1)
        }
        __syncthreads();
    }

    float sumsq = 0.f;
    #pragma unroll
    for (int i = 0; i < 2; i++)
        #pragma unroll
        for (int j = 0; j < 4; j++) {
            sumsq += acc[i][j] * acc[i][j];
            int p = pg * 4 + j, s = s0 + rg * 2 + i;
            g_textT[((size_t)(b * 32 + p)) * 512 + s] = acc[i][j];
        }

    // ---- audio: K=64, one chunk, plain loads into buffer 0 ----
    #pragma unroll
    for (int i = 0; i < 2; i++)
        #pragma unroll
        for (int j = 0; j < 4; j++) acc[i][j] = 0.f;
    #pragma unroll
    for (int q = 0; q < 4; q++) {
        int e = tid + 256 * q;
        int r = e >> 4, c = e & 15;
        float4 v = ((const float4*)ad)[(size_t)(row0 + r) * 16 + c];
        *(float4*)&sA[0][r * APITCH + c * 4] = v;
    }
    #pragma unroll
    for (int q = 0; q < 2; q++) {
        int e = tid + 256 * q;
        ((float4*)&sW[0][0])[e] = ((const float4*)g_WaT)[e];
    }
    __syncthreads();
    #pragma unroll
    for (int kk = 0; kk < 16; kk++) {
        int k = kk * 4;
        float4 A0 = *(const float4*)&sA[0][(rg * 2 + 0) * APITCH + k];
        float4 A1 = *(const float4*)&sA[0][(rg * 2 + 1) * APITCH + k];
        float4 W0 = *(const float4*)&sW[0][(k + 0) * 32 + pg * 4];
        float4 W1 = *(const float4*)&sW[0][(k + 1) * 32 + pg * 4];
        float4 W2 = *(const float4*)&sW[0][(k + 2) * 32 + pg * 4];
        float4 W3 = *(const float4*)&sW[0][(k + 3) * 32 + pg * 4];
        FSTEP(A0, 0) FSTEP(A1, 1)
    }
    #pragma unroll
    for (int i = 0; i < 2; i++)
        #pragma unroll
        for (int j = 0; j < 4; j++) {
            int p = pg * 4 + j, s = s0 + rg * 2 + i;
            g_audioT[((size_t)(b * 32 + p)) * 512 + s] = acc[i][j];
        }

    // ---- sumsq block reduce (overlay on sW[1]) ----
    __syncthreads();
    float* red = &sW[1][0];
    red[tid] = sumsq;
    __syncthreads();
    for (int s = 128; s > 0; s >>= 1) {
        if (tid < s) red[tid] += red[tid + s];
        __syncthreads();
    }
    if (tid == 0) g_part[blockIdx.x] = red[0];
}

// ------------------ K3: symmetric score matrices (+ norm prologue) ------------------
__global__ __launch_bounds__(256) void k_scores(const float* __restrict__ twp,
                                                const float* __restrict__ awp,
                                                const float* __restrict__ fbp,
                                                float* __restrict__ out_ta,
                                                float* __restrict__ out_fa) {
    __shared__ float sTs[32 * 64], sTt[32 * 64], sAs[32 * 64], sAt[32 * 64];
    __shared__ float scs;
    int x = blockIdx.x, si = 0;
    while (x >= 8 - si) { x -= 8 - si; si++; }
    int ti = si + x;
    int b = blockIdx.y;
    int s0 = si * 64, t0 = ti * 64;
    int tid = threadIdx.x;

    if (tid < 32) {
        float v = 0.f;
        #pragma unroll
        for (int j = 0; j < 8; j++) v += g_part[tid + 32 * j];
        #pragma unroll
        for (int o = 16; o > 0; o >>= 1) v += __shfl_xor_sync(0xffffffff, v, o);
        if (tid == 0) scs = rsqrtf(v);
    }

    const float4* gT = (const float4*)(g_textT  + (size_t)b * 32 * 512);
    const float4* gA = (const float4*)(g_audioT + (size_t)b * 32 * 512);
    #pragma unroll
    for (int q = 0; q < 2; q++) {
        int e = tid + 256 * q;
        int p = e >> 4, c = e & 15;
        *(float4*)&sTs[p * 64 + c * 4] = gT[p * 128 + (s0 >> 2) + c];
        *(float4*)&sTt[p * 64 + c * 4] = gT[p * 128 + (t0 >> 2) + c];
        *(float4*)&sAs[p * 64 + c * 4] = gA[p * 128 + (s0 >> 2) + c];
        *(float4*)&sAt[p * 64 + c * 4] = gA[p * 128 + (t0 >> 2) + c];
    }
    __syncthreads();

    int tx = tid & 15, ty = tid >> 4;
    float st[16], sa[16];
    #pragma unroll
    for (int i = 0; i < 16; i++) { st[i] = 0.f; sa[i] = 0.f; }

    #pragma unroll 6
    for (int p = 0; p < Pn; p++) {
        float4 a = *(float4*)&sTs[p * 64 + ty * 4];
        float4 bt = *(float4*)&sTt[p * 64 + tx * 4];
        float4 c = *(float4*)&sAs[p * 64 + ty * 4];
        float4 d = *(float4*)&sAt[p * 64 + tx * 4];
        st[0]  += a.x*bt.x; st[1]  += a.x*bt.y; st[2]  += a.x*bt.z; st[3]  += a.x*bt.w;
        st[4]  += a.y*bt.x; st[5]  += a.y*bt.y; st[6]  += a.y*bt.z; st[7]  += a.y*bt.w;
        st[8]  += a.z*bt.x; st[9]  += a.z*bt.y; st[10] += a.z*bt.z; st[11] += a.z*bt.w;
        st[12] += a.w*bt.x; st[13] += a.w*bt.y; st[14] += a.w*bt.z; st[15] += a.w*bt.w;
        sa[0]  += c.x*d.x;  sa[1]  += c.x*d.y;  sa[2]  += c.x*d.z;  sa[3]  += c.x*d.w;
        sa[4]  += c.y*d.x;  sa[5]  += c.y*d.y;  sa[6]  += c.y*d.z;  sa[7]  += c.y*d.w;
        sa[8]  += c.z*d.x;  sa[9]  += c.z*d.y;  sa[10] += c.z*d.z;  sa[11] += c.z*d.w;
        sa[12] += c.w*d.x;  sa[13] += c.w*d.y;  sa[14] += c.w*d.z;  sa[15] += c.w*d.w;
    }

    float cs = scs;
    float tw = twp[0], aw = awp[0], fb = fbp[0];
    float ta[16], fa[16];
    float rw[4];
    #pragma unroll
    for (int i = 0; i < 4; i++)
        #pragma unroll
        for (int j = 0; j < 4; j++) {
            float t_ = fmaxf(st[i * 4 + j] * cs, 0.f);
            float a_ = fmaxf(sa[i * 4 + j], 0.f);
            float r_ = tw * t_ + aw * a_ + fb;
            ta[i * 4 + j] = t_;
            fa[i * 4 + j] = fmaxf(r_, 0.f);
            if (i == 0) rw[j] = r_;
        }

    #pragma unroll
    for (int i = 0; i < 4; i++) {
        int s = s0 + ty * 4 + i;
        size_t base = ((size_t)(b * Sn + s)) * Sn + t0 + tx * 4;
        *(float4*)(out_ta + base) = make_float4(ta[i*4], ta[i*4+1], ta[i*4+2], ta[i*4+3]);
        *(float4*)(out_fa + base) = make_float4(fa[i*4], fa[i*4+1], fa[i*4+2], fa[i*4+3]);
    }
    if (si == 0 && ty == 0)
        *(float4*)(g_raw0 + b * Sn + t0 + tx * 4) =
            make_float4(rw[0], rw[1], rw[2], rw[3]);

    if (si != ti) {
        #pragma unroll
        for (int j = 0; j < 4; j++) {
            int t = t0 + tx * 4 + j;
            size_t base = ((size_t)(b * Sn + t)) * Sn + s0 + ty * 4;
            *(float4*)(out_ta + base) = make_float4(ta[j], ta[4+j], ta[8+j], ta[12+j]);
            *(float4*)(out_fa + base) = make_float4(fa[j], fa[4+j], fa[8+j], fa[12+j]);
        }
    }
}

// ------------------ K4: softmax probs for s=0 row ------------------
__global__ __launch_bounds__(256) void k_soft(const float* __restrict__ am) {
    __shared__ float red[256];
    int b = blockIdx.x, tid = threadIdx.x;
    float mbase = am[b * Sn];
    float l0 = g_raw0[b * Sn + tid]       + am[b * Sn + tid]       + mbase;
    float l1 = g_raw0[b * Sn + tid + 256] + am[b * Sn + tid + 256] + mbase;

    red[tid] = fmaxf(l0, l1);
    __syncthreads();
    for (int s = 128; s > 0; s >>= 1) {
        if (tid < s) red[tid] = fmaxf(red[tid], red[tid + s]);
        __syncthreads();
    }
    float mx = red[0];
    __syncthreads();
    float e0 = expf(l0 - mx), e1 = expf(l1 - mx);
    red[tid] = e0 + e1;
    __syncthreads();
    for (int s = 128; s > 0; s >>= 1) {
        if (tid < s) red[tid] += red[tid + s];
        __syncthreads();
    }
    float inv = 1.f / red[0];
    g_prob[b * Sn + tid]       = e0 * inv;
    g_prob[b * Sn + tid + 256] = e1 * inv;
}

// ------------------ K5: att @ hidden ------------------
__global__ __launch_bounds__(192) void k_av(const float* __restrict__ hs) {
    __shared__ float sp[32];
    int b = blockIdx.x, cy = blockIdx.y, tid = threadIdx.x;
    int t0 = cy * 32;
    if (tid < 32) sp[tid] = g_prob[b * Sn + t0 + tid];
    __syncthreads();

    const float4* hb = (const float4*)(hs + (size_t)b * Sn * Hn);
    float4 acc = make_float4(0.f, 0.f, 0.f, 0.f);
    #pragma unroll 4
    for (int t = 0; t < 32; t++) {
        float p = sp[t];
        float4 h = hb[(size_t)(t0 + t) * 192 + tid];
        acc.x += p * h.x; acc.y += p * h.y; acc.z += p * h.z; acc.w += p * h.w;
    }
    ((float4*)g_avp)[(size_t)(b * 16 + cy) * 192 + tid] = acc;
}

// ------------------ K6: dense GEMV ------------------
__global__ __launch_bounds__(256) void k_dense(const float* __restrict__ hs,
                                               const float* __restrict__ Wd,
                                               const float* __restrict__ bd) {
    __shared__ float sx[Hn];
    int b = blockIdx.x, oc = blockIdx.y, tid = threadIdx.x;
    int w = tid >> 5, lane = tid & 31;

    for (int i = tid; i < Hn; i += 256) {
        float v = hs[(size_t)b * Sn * Hn + i];
        #pragma unroll
        for (int c = 0; c < 16; c++) v += g_avp[(size_t)(b * 16 + c) * Hn + i];
        sx[i] = v;
    }
    __syncthreads();

    const float4* sx4 = (const float4*)sx;
    #pragma unroll
    for (int q = 0; q < 12; q++) {
        int o = oc * 96 + w * 12 + q;
        const float4* w4 = (const float4*)(Wd + (size_t)o * Hn);
        float acc = 0.f;
        #pragma unroll
        for (int c = 0; c < 6; c++) {
            float4 wv = w4[c * 32 + lane];
            float4 xv = sx4[c * 32 + lane];
            acc += wv.x * xv.x + wv.y * xv.y + wv.z * xv.z + wv.w * xv.w;
        }
        #pragma unroll
        for (int s = 16; s > 0; s >>= 1)
            acc += __shfl_down_sync(0xffffffff, acc, s);
        if (lane == 0) g_h[b * Hn + o] = acc + bd[o];
    }
}

// ------------------ K7: layernorm ------------------
__global__ __launch_bounds__(256) void k_ln(const float* __restrict__ lw,
                                            const float* __restrict__ lb,
                                            float* __restrict__ out0) {
    __shared__ float red[256];
    int b = blockIdx.x, tid = threadIdx.x;
    float hv[3];
    #pragma unroll
    for (int j = 0; j < 3; j++) hv[j] = g_h[b * Hn + tid + 256 * j];

    red[tid] = hv[0] + hv[1] + hv[2];
    __syncthreads();
    for (int s = 128; s > 0; s >>= 1) {
        if (tid < s) red[tid] += red[tid + s];
        __syncthreads();
    }
    float u = red[0] / (float)Hn;
    __syncthreads();
    float vs = 0.f;
    #pragma unroll
    for (int j = 0; j < 3; j++) { float d = hv[j] - u; vs += d * d; }
    red[tid] = vs;
    __syncthreads();
    for (int s = 128; s > 0; s >>= 1) {
        if (tid < s) red[tid] += red[tid + s];
        __syncthreads();
    }
    float rstd = rsqrtf(red[0] / (float)Hn + 1e-12f);
    #pragma unroll
    for (int j = 0; j < 3; j++) {
        int o = tid + 256 * j;
        out0[b * Hn + o] = lw[o] * (hv[j] - u) * rstd + lb[o];
    }
}

// ------------------ launch ------------------
extern "C" void kernel_launch(void* const* d_in, const int* in_sizes, int n_in,
                              void* d_out, int out_size) {
    const float* hs = (const float*)d_in[0];
    const float* ad = (const float*)d_in[1];
    const float* am = (const float*)d_in[2];
    const float* Wt = (const float*)d_in[3];
    const float* Wa = (const float*)d_in[4];
    const float* tw = (const float*)d_in[5];
    const float* aw = (const float*)d_in[6];
    const float* fb = (const float*)d_in[7];
    const float* Wd = (const float*)d_in[8];
    const float* bd = (const float*)d_in[9];
    const float* lw = (const float*)d_in[10];
    const float* lb = (const float*)d_in[11];

    float* out    = (float*)d_out;
    float* out_h0 = out;
    float* out_ta = out + Bn * Hn;
    float* out_fa = out + Bn * Hn + (size_t)Bn * Sn * Sn;

    k_prep_t0<<<48, 256>>>(Wt);
    k_prep_t1<<<48, 256>>>(Wt);
    k_prep_a<<<8, 256>>>(Wa);
    k_proj<<<256, 256>>>(hs, ad);             // 4th launch -> gets profiled
    k_scores<<<dim3(36, 32), 256>>>(tw, aw, fb, out_ta, out_fa);
    k_soft<<<32, 256>>>(am);
    k_av<<<dim3(32, 16), 192>>>(hs);
    k_dense<<<dim3(32, 8), 256>>>(hs, Wd, bd);
    k_ln<<<32, 256>>>(lw, lb, out_h0);
}

// round 14
// speedup vs baseline: 1.7297x; 1.0365x over previous
#include <cuda_runtime.h>
#include <stdint.h>
#include <math.h>

#define Bn 32
#define Sn 512
#define Hn 768
#define FDn 64
#define Pn 30
#define NROWS (Bn*Sn)    // 16384

typedef unsigned long long u64;

__device__ __forceinline__ void fma2(u64 &d, u64 a, u64 b) {
    asm("fma.rn.f32x2 %0, %1, %2, %0;" : "+l"(d) : "l"(a), "l"(b));
}
__device__ __forceinline__ u64 rep2(float a) {
    u64 r; asm("mov.b64 %0, {%1, %1};" : "=l"(r) : "f"(a)); return r;
}
__device__ __forceinline__ float2 unpk(u64 v) {
    float2 f; asm("mov.b64 {%0, %1}, %2;" : "=f"(f.x), "=f"(f.y) : "l"(v)); return f;
}

// ------------------ scratch ------------------
__device__ float g_WT [Hn * 32];          // W_t transposed [k][p], zero-padded p
__device__ float g_WaT[FDn * 32];         // W_a transposed [k][p]
__device__ float g_textT [Bn * 32 * Sn];  // [b][p][s]
__device__ float g_audioT[Bn * 32 * Sn];  // [b][p][s]
__device__ float g_part[256];             // block partial sums of text^2
__device__ float g_raw0[Bn * Sn];
__device__ float g_prob[Bn * Sn];
__device__ float g_avp[Bn * 16 * Hn];
__device__ float g_h[Bn * Hn];

// ------------------ K0a/K0b/K0c: transpose weights ------------------
__global__ void k_prep_t0(const float* __restrict__ Wt) {
    int e = blockIdx.x * 256 + threadIdx.x;      // first 12288
    int p = e & 31, k = e >> 5;
    g_WT[e] = (p < Pn) ? Wt[p * Hn + k] : 0.f;
}
__global__ void k_prep_t1(const float* __restrict__ Wt) {
    int e = 12288 + blockIdx.x * 256 + threadIdx.x;   // second 12288
    int p = e & 31, k = e >> 5;
    g_WT[e] = (p < Pn) ? Wt[p * Hn + k] : 0.f;
}
__global__ void k_prep_a(const float* __restrict__ Wa) {
    int e = blockIdx.x * 256 + threadIdx.x;      // 2048
    int p = e & 31, k = e >> 5;
    g_WaT[e] = (p < Pn) ? Wa[p * FDn + k] : 0.f;
}

// ------------------ K1: projection GEMM, f32x2 2r x 8p, cp.async double-buffered ------------------
// grid 256 (64-row tiles), block 128. Thread: rows rthr*2+{0,1}, p = pthr*8..pthr*8+7.
#define APITCH 68

__device__ __forceinline__ void cp16(unsigned int dst, const void* src) {
    asm volatile("cp.async.cg.shared.global [%0], [%1], 16;" :: "r"(dst), "l"(src));
}

__global__ __launch_bounds__(128) void k_proj(const float* __restrict__ hs,
                                              const float* __restrict__ ad) {
    __shared__ __align__(16) float sA[2][64 * APITCH];   // 34 KB
    __shared__ __align__(16) float sW[2][64 * 32];       // 16 KB
    int tid = threadIdx.x;
    int pthr = tid & 3, rthr = tid >> 2;   // rthr 0..31, pthr 0..3
    int row0 = blockIdx.x * 64;
    int b = row0 >> 9, s0 = row0 & 511;
    const float4* hs4 = (const float4*)hs;
    const float4* gW4 = (const float4*)g_WT;

    unsigned int aA[2], aW[2];
    aA[0] = (unsigned int)__cvta_generic_to_shared(&sA[0][0]);
    aA[1] = (unsigned int)__cvta_generic_to_shared(&sA[1][0]);
    aW[0] = (unsigned int)__cvta_generic_to_shared(&sW[0][0]);
    aW[1] = (unsigned int)__cvta_generic_to_shared(&sW[1][0]);

    // prefetch chunk 0
    #pragma unroll
    for (int q = 0; q < 8; q++) {
        int e = tid + 128 * q;             // 1024 float4: A 64x64
        int r = e >> 4, c = e & 15;
        cp16(aA[0] + (unsigned int)(r * APITCH + c * 4) * 4,
             &hs4[(size_t)(row0 + r) * 192 + c]);
    }
    #pragma unroll
    for (int q = 0; q < 4; q++) {
        int e = tid + 128 * q;             // 512 float4: W 64x32
        cp16(aW[0] + (unsigned int)e * 16, &gW4[e]);
    }
    asm volatile("cp.async.commit_group;");

    u64 acc[2][4];
    #pragma unroll
    for (int i = 0; i < 2; i++)
        #pragma unroll
        for (int j = 0; j < 4; j++) acc[i][j] = 0ull;

    for (int kc = 0; kc < 12; kc++) {
        int cur = kc & 1;
        if (kc < 11) {
            int nb = cur ^ 1;
            #pragma unroll
            for (int q = 0; q < 8; q++) {
                int e = tid + 128 * q;
                int r = e >> 4, c = e & 15;
                cp16(aA[nb] + (unsigned int)(r * APITCH + c * 4) * 4,
                     &hs4[(size_t)(row0 + r) * 192 + (kc + 1) * 16 + c]);
            }
            #pragma unroll
            for (int q = 0; q < 4; q++) {
                int e = tid + 128 * q;
                cp16(aW[nb] + (unsigned int)e * 16, &gW4[(kc + 1) * 512 + e]);
            }
            asm volatile("cp.async.commit_group;");
            asm volatile("cp.async.wait_group 1;");
        } else {
            asm volatile("cp.async.wait_group 0;");
        }
        __syncthreads();

        const float* pA = sA[cur];
        const float* pW = sW[cur];
        #pragma unroll 16
        for (int k = 0; k < 64; k++) {
            const u64* wp = (const u64*)&pW[k * 32 + pthr * 8];
            u64 w0 = wp[0], w1 = wp[1], w2 = wp[2], w3 = wp[3];
            u64 r0 = rep2(pA[(rthr * 2 + 0) * APITCH + k]);
            u64 r1 = rep2(pA[(rthr * 2 + 1) * APITCH + k]);
            fma2(acc[0][0], r0, w0); fma2(acc[0][1], r0, w1);
            fma2(acc[0][2], r0, w2); fma2(acc[0][3], r0, w3);
            fma2(acc[1][0], r1, w0); fma2(acc[1][1], r1, w1);
            fma2(acc[1][2], r1, w2); fma2(acc[1][3], r1, w3);
        }
        __syncthreads();
    }

    float sumsq = 0.f;
    #pragma unroll
    for (int i = 0; i < 2; i++)
        #pragma unroll
        for (int j = 0; j < 4; j++) {
            float2 f = unpk(acc[i][j]);
            sumsq += f.x * f.x + f.y * f.y;
            int p = pthr * 8 + 2 * j, s = s0 + rthr * 2 + i;
            g_textT[((size_t)(b * 32 + p))     * 512 + s] = f.x;
            g_textT[((size_t)(b * 32 + p + 1)) * 512 + s] = f.y;
        }

    // ---- audio: K=64, one chunk, plain loads into buffer 0 ----
    u64 aacc[2][4];
    #pragma unroll
    for (int i = 0; i < 2; i++)
        #pragma unroll
        for (int j = 0; j < 4; j++) aacc[i][j] = 0ull;
    #pragma unroll
    for (int q = 0; q < 8; q++) {
        int e = tid + 128 * q;
        int r = e >> 4, c = e & 15;
        float4 v = ((const float4*)ad)[(size_t)(row0 + r) * 16 + c];
        *(float4*)&sA[0][r * APITCH + c * 4] = v;
    }
    #pragma unroll
    for (int q = 0; q < 4; q++) {
        int e = tid + 128 * q;
        ((float4*)&sW[0][0])[e] = ((const float4*)g_WaT)[e];
    }
    __syncthreads();
    {
        const float* pA = sA[0];
        const float* pW = sW[0];
        #pragma unroll 16
        for (int k = 0; k < 64; k++) {
            const u64* wp = (const u64*)&pW[k * 32 + pthr * 8];
            u64 w0 = wp[0], w1 = wp[1], w2 = wp[2], w3 = wp[3];
            u64 r0 = rep2(pA[(rthr * 2 + 0) * APITCH + k]);
            u64 r1 = rep2(pA[(rthr * 2 + 1) * APITCH + k]);
            fma2(aacc[0][0], r0, w0); fma2(aacc[0][1], r0, w1);
            fma2(aacc[0][2], r0, w2); fma2(aacc[0][3], r0, w3);
            fma2(aacc[1][0], r1, w0); fma2(aacc[1][1], r1, w1);
            fma2(aacc[1][2], r1, w2); fma2(aacc[1][3], r1, w3);
        }
    }
    #pragma unroll
    for (int i = 0; i < 2; i++)
        #pragma unroll
        for (int j = 0; j < 4; j++) {
            float2 f = unpk(aacc[i][j]);
            int p = pthr * 8 + 2 * j, s = s0 + rthr * 2 + i;
            g_audioT[((size_t)(b * 32 + p))     * 512 + s] = f.x;
            g_audioT[((size_t)(b * 32 + p + 1)) * 512 + s] = f.y;
        }

    // ---- sumsq block reduce (overlay on sW[1]) ----
    __syncthreads();
    float* red = &sW[1][0];
    red[tid] = sumsq;
    __syncthreads();
    for (int s = 64; s > 0; s >>= 1) {
        if (tid < s) red[tid] += red[tid + s];
        __syncthreads();
    }
    if (tid == 0) g_part[blockIdx.x] = red[0];
}

// ------------------ K3: symmetric score matrices (+ norm prologue) ------------------
__global__ __launch_bounds__(256) void k_scores(const float* __restrict__ twp,
                                                const float* __restrict__ awp,
                                                const float* __restrict__ fbp,
                                                float* __restrict__ out_ta,
                                                float* __restrict__ out_fa) {
    __shared__ float sTs[32 * 64], sTt[32 * 64], sAs[32 * 64], sAt[32 * 64];
    __shared__ float scs;
    int x = blockIdx.x, si = 0;
    while (x >= 8 - si) { x -= 8 - si; si++; }
    int ti = si + x;
    int b = blockIdx.y;
    int s0 = si * 64, t0 = ti * 64;
    int tid = threadIdx.x;

    if (tid < 32) {
        float v = 0.f;
        #pragma unroll
        for (int j = 0; j < 8; j++) v += g_part[tid + 32 * j];
        #pragma unroll
        for (int o = 16; o > 0; o >>= 1) v += __shfl_xor_sync(0xffffffff, v, o);
        if (tid == 0) scs = rsqrtf(v);
    }

    const float4* gT = (const float4*)(g_textT  + (size_t)b * 32 * 512);
    const float4* gA = (const float4*)(g_audioT + (size_t)b * 32 * 512);
    #pragma unroll
    for (int q = 0; q < 2; q++) {
        int e = tid + 256 * q;
        int p = e >> 4, c = e & 15;
        *(float4*)&sTs[p * 64 + c * 4] = gT[p * 128 + (s0 >> 2) + c];
        *(float4*)&sTt[p * 64 + c * 4] = gT[p * 128 + (t0 >> 2) + c];
        *(float4*)&sAs[p * 64 + c * 4] = gA[p * 128 + (s0 >> 2) + c];
        *(float4*)&sAt[p * 64 + c * 4] = gA[p * 128 + (t0 >> 2) + c];
    }
    __syncthreads();

    int tx = tid & 15, ty = tid >> 4;
    float st[16], sa[16];
    #pragma unroll
    for (int i = 0; i < 16; i++) { st[i] = 0.f; sa[i] = 0.f; }

    #pragma unroll 6
    for (int p = 0; p < Pn; p++) {
        float4 a = *(float4*)&sTs[p * 64 + ty * 4];
        float4 bt = *(float4*)&sTt[p * 64 + tx * 4];
        float4 c = *(float4*)&sAs[p * 64 + ty * 4];
        float4 d = *(float4*)&sAt[p * 64 + tx * 4];
        st[0]  += a.x*bt.x; st[1]  += a.x*bt.y; st[2]  += a.x*bt.z; st[3]  += a.x*bt.w;
        st[4]  += a.y*bt.x; st[5]  += a.y*bt.y; st[6]  += a.y*bt.z; st[7]  += a.y*bt.w;
        st[8]  += a.z*bt.x; st[9]  += a.z*bt.y; st[10] += a.z*bt.z; st[11] += a.z*bt.w;
        st[12] += a.w*bt.x; st[13] += a.w*bt.y; st[14] += a.w*bt.z; st[15] += a.w*bt.w;
        sa[0]  += c.x*d.x;  sa[1]  += c.x*d.y;  sa[2]  += c.x*d.z;  sa[3]  += c.x*d.w;
        sa[4]  += c.y*d.x;  sa[5]  += c.y*d.y;  sa[6]  += c.y*d.z;  sa[7]  += c.y*d.w;
        sa[8]  += c.z*d.x;  sa[9]  += c.z*d.y;  sa[10] += c.z*d.z;  sa[11] += c.z*d.w;
        sa[12] += c.w*d.x;  sa[13] += c.w*d.y;  sa[14] += c.w*d.z;  sa[15] += c.w*d.w;
    }

    float cs = scs;
    float tw = twp[0], aw = awp[0], fb = fbp[0];
    float ta[16], fa[16];
    float rw[4];
    #pragma unroll
    for (int i = 0; i < 4; i++)
        #pragma unroll
        for (int j = 0; j < 4; j++) {
            float t_ = fmaxf(st[i * 4 + j] * cs, 0.f);
            float a_ = fmaxf(sa[i * 4 + j], 0.f);
            float r_ = tw * t_ + aw * a_ + fb;
            ta[i * 4 + j] = t_;
            fa[i * 4 + j] = fmaxf(r_, 0.f);
            if (i == 0) rw[j] = r_;
        }

    #pragma unroll
    for (int i = 0; i < 4; i++) {
        int s = s0 + ty * 4 + i;
        size_t base = ((size_t)(b * Sn + s)) * Sn + t0 + tx * 4;
        *(float4*)(out_ta + base) = make_float4(ta[i*4], ta[i*4+1], ta[i*4+2], ta[i*4+3]);
        *(float4*)(out_fa + base) = make_float4(fa[i*4], fa[i*4+1], fa[i*4+2], fa[i*4+3]);
    }
    if (si == 0 && ty == 0)
        *(float4*)(g_raw0 + b * Sn + t0 + tx * 4) =
            make_float4(rw[0], rw[1], rw[2], rw[3]);

    if (si != ti) {
        #pragma unroll
        for (int j = 0; j < 4; j++) {
            int t = t0 + tx * 4 + j;
            size_t base = ((size_t)(b * Sn + t)) * Sn + s0 + ty * 4;
            *(float4*)(out_ta + base) = make_float4(ta[j], ta[4+j], ta[8+j], ta[12+j]);
            *(float4*)(out_fa + base) = make_float4(fa[j], fa[4+j], fa[8+j], fa[12+j]);
        }
    }
}

// ------------------ K4: softmax probs for s=0 row ------------------
__global__ __launch_bounds__(256) void k_soft(const float* __restrict__ am) {
    __shared__ float red[256];
    int b = blockIdx.x, tid = threadIdx.x;
    float mbase = am[b * Sn];
    float l0 = g_raw0[b * Sn + tid]       + am[b * Sn + tid]       + mbase;
    float l1 = g_raw0[b * Sn + tid + 256] + am[b * Sn + tid + 256] + mbase;

    red[tid] = fmaxf(l0, l1);
    __syncthreads();
    for (int s = 128; s > 0; s >>= 1) {
        if (tid < s) red[tid] = fmaxf(red[tid], red[tid + s]);
        __syncthreads();
    }
    float mx = red[0];
    __syncthreads();
    float e0 = expf(l0 - mx), e1 = expf(l1 - mx);
    red[tid] = e0 + e1;
    __syncthreads();
    for (int s = 128; s > 0; s >>= 1) {
        if (tid < s) red[tid] += red[tid + s];
        __syncthreads();
    }
    float inv = 1.f / red[0];
    g_prob[b * Sn + tid]       = e0 * inv;
    g_prob[b * Sn + tid + 256] = e1 * inv;
}

// ------------------ K5: att @ hidden ------------------
__global__ __launch_bounds__(192) void k_av(const float* __restrict__ hs) {
    __shared__ float sp[32];
    int b = blockIdx.x, cy = blockIdx.y, tid = threadIdx.x;
    int t0 = cy * 32;
    if (tid < 32) sp[tid] = g_prob[b * Sn + t0 + tid];
    __syncthreads();

    const float4* hb = (const float4*)(hs + (size_t)b * Sn * Hn);
    float4 acc = make_float4(0.f, 0.f, 0.f, 0.f);
    #pragma unroll 4
    for (int t = 0; t < 32; t++) {
        float p = sp[t];
        float4 h = hb[(size_t)(t0 + t) * 192 + tid];
        acc.x += p * h.x; acc.y += p * h.y; acc.z += p * h.z; acc.w += p * h.w;
    }
    ((float4*)g_avp)[(size_t)(b * 16 + cy) * 192 + tid] = acc;
}

// ------------------ K6: dense GEMV ------------------
__global__ __launch_bounds__(256) void k_dense(const float* __restrict__ hs,
                                               const float* __restrict__ Wd,
                                               const float* __restrict__ bd) {
    __shared__ float sx[Hn];
    int b = blockIdx.x, oc = blockIdx.y, tid = threadIdx.x;
    int w = tid >> 5, lane = tid & 31;

    for (int i = tid; i < Hn; i += 256) {
        float v = hs[(size_t)b * Sn * Hn + i];
        #pragma unroll
        for (int c = 0; c < 16; c++) v += g_avp[(size_t)(b * 16 + c) * Hn + i];
        sx[i] = v;
    }
    __syncthreads();

    const float4* sx4 = (const float4*)sx;
    #pragma unroll
    for (int q = 0; q < 12; q++) {
        int o = oc * 96 + w * 12 + q;
        const float4* w4 = (const float4*)(Wd + (size_t)o * Hn);
        float acc = 0.f;
        #pragma unroll
        for (int c = 0; c < 6; c++) {
            float4 wv = w4[c * 32 + lane];
            float4 xv = sx4[c * 32 + lane];
            acc += wv.x * xv.x + wv.y * xv.y + wv.z * xv.z + wv.w * xv.w;
        }
        #pragma unroll
        for (int s = 16; s > 0; s >>= 1)
            acc += __shfl_down_sync(0xffffffff, acc, s);
        if (lane == 0) g_h[b * Hn + o] = acc + bd[o];
    }
}

// ------------------ K7: layernorm ------------------
__global__ __launch_bounds__(256) void k_ln(const float* __restrict__ lw,
                                            const float* __restrict__ lb,
                                            float* __restrict__ out0) {
    __shared__ float red[256];
    int b = blockIdx.x, tid = threadIdx.x;
    float hv[3];
    #pragma unroll
    for (int j = 0; j < 3; j++) hv[j] = g_h[b * Hn + tid + 256 * j];

    red[tid] = hv[0] + hv[1] + hv[2];
    __syncthreads();
    for (int s = 128; s > 0; s >>= 1) {
        if (tid < s) red[tid] += red[tid + s];
        __syncthreads();
    }
    float u = red[0] / (float)Hn;
    __syncthreads();
    float vs = 0.f;
    #pragma unroll
    for (int j = 0; j < 3; j++) { float d = hv[j] - u; vs += d * d; }
    red[tid] = vs;
    __syncthreads();
    for (int s = 128; s > 0; s >>= 1) {
        if (tid < s) red[tid] += red[tid + s];
        __syncthreads();
    }
    float rstd = rsqrtf(red[0] / (float)Hn + 1e-12f);
    #pragma unroll
    for (int j = 0; j < 3; j++) {
        int o = tid + 256 * j;
        out0[b * Hn + o] = lw[o] * (hv[j] - u) * rstd + lb[o];
    }
}

// ------------------ launch ------------------
extern "C" void kernel_launch(void* const* d_in, const int* in_sizes, int n_in,
                              void* d_out, int out_size) {
    const float* hs = (const float*)d_in[0];
    const float* ad = (const float*)d_in[1];
    const float* am = (const float*)d_in[2];
    const float* Wt = (const float*)d_in[3];
    const float* Wa = (const float*)d_in[4];
    const float* tw = (const float*)d_in[5];
    const float* aw = (const float*)d_in[6];
    const float* fb = (const float*)d_in[7];
    const float* Wd = (const float*)d_in[8];
    const float* bd = (const float*)d_in[9];
    const float* lw = (const float*)d_in[10];
    const float* lb = (const float*)d_in[11];

    float* out    = (float*)d_out;
    float* out_h0 = out;
    float* out_ta = out + Bn * Hn;
    float* out_fa = out + Bn * Hn + (size_t)Bn * Sn * Sn;

    k_prep_t0<<<48, 256>>>(Wt);
    k_prep_t1<<<48, 256>>>(Wt);
    k_prep_a<<<8, 256>>>(Wa);
    k_proj<<<256, 128>>>(hs, ad);             // 4th launch -> gets profiled
    k_scores<<<dim3(36, 32), 256>>>(tw, aw, fb, out_ta, out_fa);
    k_soft<<<32, 256>>>(am);
    k_av<<<dim3(32, 16), 192>>>(hs);
    k_dense<<<dim3(32, 8), 256>>>(hs, Wd, bd);
    k_ln<<<32, 256>>>(lw, lb, out_h0);
}